// round 1
// baseline (speedup 1.0000x reference)
#include <cuda_runtime.h>
#include <math.h>

#define NB 2
#define NT 16
#define NH 64
#define NW 64
#define NC 64
#define HW 4096      // NH*NW
#define THW 65536    // NT*HW
#define TOT 8388608  // NB*NC*THW

// Scratch (allocation-free rule: __device__ globals).
// g_xr: real x transposed to (b,c,t,h,w); later reused for real IFFT output.
static __device__ float  g_xr[TOT];
static __device__ float  g_fg[TOT];   // forget gate, (b,c,t,h,w)
static __device__ float  g_gt[TOT];   // input_gate * delta, (b,c,t,h,w)
static __device__ float2 g_xf[TOT];   // complex work array (b,c,t,h,w)

__device__ __forceinline__ float2 cmul(float2 a, float2 b){
    return make_float2(a.x*b.x - a.y*b.y, a.x*b.y + a.y*b.x);
}
__device__ __forceinline__ float2 cadd(float2 a, float2 b){ return make_float2(a.x+b.x, a.y+b.y); }
__device__ __forceinline__ float2 csub(float2 a, float2 b){ return make_float2(a.x-b.x, a.y-b.y); }

// ---------------- P1: gates + delta GEMM + transpose ----------------
// block = one (b,t,h) row: 64(w) x 64(c) tile
__global__ __launch_bounds__(256) void k_gates(
    const float* __restrict__ x, const float* __restrict__ dW,
    const float* __restrict__ db, const float* __restrict__ fb,
    const float* __restrict__ fs, const float* __restrict__ ib,
    const float* __restrict__ isc)
{
    __shared__ float Xs[64][65];   // [w][c]
    __shared__ float Ds[64][65];   // [w][d]  (softplus(delta))
    int tid = threadIdx.x;
    int blk = blockIdx.x;                  // ((b*16+t)*64 + h)
    int h = blk & 63, bt = blk >> 6, t = bt & 15, b = bt >> 4;
    const float* xrow = x + (size_t)blk * (NW*NC);

    for (int idx = tid; idx < 4096; idx += 256)
        Xs[idx >> 6][idx & 63] = xrow[idx];
    __syncthreads();

    // 4x4 register-tiled matvec: delta[w][d] = sum_c Xs[w][c] * dW[c][d]
    int d0 = (tid & 15) << 2;
    int w0 = (tid >> 4) << 2;
    float acc[4][4];
    #pragma unroll
    for (int i=0;i<4;i++)
        #pragma unroll
        for (int j=0;j<4;j++) acc[i][j] = 0.f;
    #pragma unroll 4
    for (int c=0;c<64;c++){
        float4 wv = __ldg((const float4*)(dW + c*64 + d0));
        float xs0 = Xs[w0+0][c], xs1 = Xs[w0+1][c];
        float xs2 = Xs[w0+2][c], xs3 = Xs[w0+3][c];
        acc[0][0]=fmaf(xs0,wv.x,acc[0][0]); acc[0][1]=fmaf(xs0,wv.y,acc[0][1]);
        acc[0][2]=fmaf(xs0,wv.z,acc[0][2]); acc[0][3]=fmaf(xs0,wv.w,acc[0][3]);
        acc[1][0]=fmaf(xs1,wv.x,acc[1][0]); acc[1][1]=fmaf(xs1,wv.y,acc[1][1]);
        acc[1][2]=fmaf(xs1,wv.z,acc[1][2]); acc[1][3]=fmaf(xs1,wv.w,acc[1][3]);
        acc[2][0]=fmaf(xs2,wv.x,acc[2][0]); acc[2][1]=fmaf(xs2,wv.y,acc[2][1]);
        acc[2][2]=fmaf(xs2,wv.z,acc[2][2]); acc[2][3]=fmaf(xs2,wv.w,acc[2][3]);
        acc[3][0]=fmaf(xs3,wv.x,acc[3][0]); acc[3][1]=fmaf(xs3,wv.y,acc[3][1]);
        acc[3][2]=fmaf(xs3,wv.z,acc[3][2]); acc[3][3]=fmaf(xs3,wv.w,acc[3][3]);
    }
    #pragma unroll
    for (int j=0;j<4;j++){
        float bias = __ldg(db + d0 + j);
        #pragma unroll
        for (int i=0;i<4;i++){
            float z = acc[i][j] + bias;
            Ds[w0+i][d0+j] = (z > 20.f) ? z : log1pf(__expf(z));  // softplus
        }
    }
    __syncthreads();

    // write xr, fg, g in (b,c,t,h,w) layout (w-contiguous per c)
    size_t obase = (size_t)b*((size_t)NC*THW) + (size_t)t*HW + (size_t)h*NW;
    for (int idx = tid; idx < 4096; idx += 256){
        int c = idx >> 6, w = idx & 63;
        float xv = Xs[w][c];
        size_t o = obase + (size_t)c*THW + w;
        g_xr[o] = xv;
        float fgv = 1.f/(1.f + __expf(-(__ldg(fb+c)  + __ldg(fs+c) *xv)));
        float igv = 1.f/(1.f + __expf(-(__ldg(ib+c)  + __ldg(isc+c)*xv)));
        g_fg[o] = fgv;
        g_gt[o] = igv * Ds[w][c];
    }
}

// ---------------- 64-pt batched FFT in smem (fused radix-2^2) ----------------
// 64 FFTs over a 64x65-padded float2 tile. Element i of fft r at S[r*rs + i*es].
template<bool INV>
__device__ __forceinline__ void fft64_batch(float2* S, const float2* tw, int tid, int rs, int es)
{
    // bit-reverse (6 bits)
    for (int idx = tid; idx < 4096; idx += 256){
        int r = idx >> 6, i = idx & 63;
        int j = __brev(i) >> 26;
        if (i < j){
            float2 a = S[r*rs + i*es];
            S[r*rs + i*es] = S[r*rs + j*es];
            S[r*rs + j*es] = a;
        }
    }
    __syncthreads();
    #pragma unroll
    for (int st = 0; st < 3; ++st){
        const int m  = 1 << (2*st + 1);   // 2, 8, 32
        const int mh = m >> 1;
        for (int idx = tid; idx < 1024; idx += 256){
            int r = idx >> 4, u = idx & 15;
            int j = u & (mh - 1);
            int g = u >> (2*st);
            int q0 = g*(m<<1) + j;
            float2* p = S + r*rs;
            float2 a  = p[(q0      )*es];
            float2 b1 = p[(q0+mh   )*es];
            float2 c1 = p[(q0+m    )*es];
            float2 d1 = p[(q0+m+mh )*es];
            float2 w1 = tw[j * (64/m)];
            float2 w2 = tw[j * (32/m)];
            float2 w3 = tw[j * (32/m) + 16];
            if (INV){ w1.y = -w1.y; w2.y = -w2.y; w3.y = -w3.y; }
            float2 tb = cmul(b1, w1);
            float2 td = cmul(d1, w1);
            float2 e0 = cadd(a, tb),  e1 = csub(a, tb);
            float2 e2 = cadd(c1, td), e3 = csub(c1, td);
            float2 f2 = cmul(e2, w2);
            float2 f3 = cmul(e3, w3);
            p[(q0      )*es] = cadd(e0, f2);
            p[(q0+m    )*es] = csub(e0, f2);
            p[(q0+mh   )*es] = cadd(e1, f3);
            p[(q0+m+mh )*es] = csub(e1, f3);
        }
        __syncthreads();
    }
}

// ---------------- P2: forward 2D FFT (h,w) per (b,c,t) slice ----------------
__global__ __launch_bounds__(256) void k_fft_fwd()
{
    __shared__ float2 S[64*65];
    __shared__ float2 tw[32];
    int tid = threadIdx.x;
    if (tid < 32){
        float s, c;
        sincosf(-6.283185307179586f * (float)tid / 64.f, &s, &c);
        tw[tid] = make_float2(c, s);
    }
    const float* src = g_xr + (size_t)blockIdx.x * HW;
    float2* dst = g_xf + (size_t)blockIdx.x * HW;
    for (int idx = tid; idx < 4096; idx += 256)
        S[(idx >> 6)*65 + (idx & 63)] = make_float2(src[idx], 0.f);
    __syncthreads();
    fft64_batch<false>(S, tw, tid, 65, 1);   // along w
    fft64_batch<false>(S, tw, tid, 1, 65);   // along h
    for (int idx = tid; idx < 4096; idx += 256)
        dst[idx] = S[(idx >> 6)*65 + (idx & 63)];
}

// ---------------- 16-pt register FFT ----------------
template<bool INV>
__device__ __forceinline__ void fft16r(float2* v, const float2* tw)
{
    const int rev[16] = {0,8,4,12,2,10,6,14,1,9,5,13,3,11,7,15};
    #pragma unroll
    for (int i=0;i<16;i++){
        int j = rev[i];
        if (i < j){ float2 tmp = v[i]; v[i] = v[j]; v[j] = tmp; }
    }
    #pragma unroll
    for (int st=1; st<=4; ++st){
        const int m = 1<<st, mh = m>>1;
        #pragma unroll
        for (int g=0; g<16; g+=m){
            #pragma unroll
            for (int j=0;j<mh;++j){
                float2 w = tw[j*(16/m)];
                if (INV) w.y = -w.y;
                float2 u = v[g+j];
                float2 t2 = cmul(v[g+j+mh], w);
                v[g+j]    = cadd(u, t2);
                v[g+j+mh] = csub(u, t2);
            }
        }
    }
}

// ---------------- P3: T-FFT + Mamba scan + T-IFFT (fused, in registers) ----
__global__ __launch_bounds__(256) void k_tscan(const float* __restrict__ Ak,
                                               const float* __restrict__ Bk)
{
    __shared__ float sKA[27], sKB[27];
    int tid = threadIdx.x;
    int c = blockIdx.y, b = blockIdx.z;
    if (tid < 27){ sKA[tid] = Ak[c*27+tid]; sKB[tid] = Bk[c*27+tid]; }
    __syncthreads();
    int hw = blockIdx.x*256 + tid;
    int h = hw >> 6, w = hw & 63;

    float2 tw16[8];
    #pragma unroll
    for (int k=0;k<8;k++){
        float s, cc; sincosf(-0.39269908169872414f*(float)k, &s, &cc);   // -2pi/16 * k
        tw16[k] = make_float2(cc, s);
    }
    float2 eh, ew;
    { float s,cc; sincosf(-0.09817477042468103f*(float)h, &s, &cc); eh = make_float2(cc,s); } // -2pi/64*h
    { float s,cc; sincosf(-0.09817477042468103f*(float)w, &s, &cc); ew = make_float2(cc,s); }
    float2 eh3[3] = { make_float2(eh.x,-eh.y), make_float2(1.f,0.f), eh };
    float2 ew3[3] = { make_float2(ew.x,-ew.y), make_float2(1.f,0.f), ew };

    // collapse 3x3 spatial taps: s[dt] = sum_{dh,dw} K[dt,dh,dw] * eh^(dh-1) * ew^(dw-1)
    float2 sA[3], sB[3];
    #pragma unroll
    for (int dt=0;dt<3;dt++){
        float2 a = make_float2(0.f,0.f), bb = make_float2(0.f,0.f);
        #pragma unroll
        for (int dh=0;dh<3;dh++){
            #pragma unroll
            for (int dw=0;dw<3;dw++){
                float2 e = cmul(eh3[dh], ew3[dw]);
                float ka = sKA[dt*9+dh*3+dw], kb = sKB[dt*9+dh*3+dw];
                a.x  = fmaf(ka, e.x, a.x);  a.y  = fmaf(ka, e.y, a.y);
                bb.x = fmaf(kb, e.x, bb.x); bb.y = fmaf(kb, e.y, bb.y);
            }
        }
        sA[dt]=a; sB[dt]=bb;
    }

    size_t base = ((size_t)(b*NC + c))*THW + (size_t)hw;
    float2 v[16];
    #pragma unroll
    for (int t=0;t<16;t++) v[t] = g_xf[base + (size_t)t*HW];
    fft16r<false>(v, tw16);

    float2 hacc = make_float2(0.f, 0.f);
    #pragma unroll
    for (int t=0;t<16;t++){
        float fgv = g_fg[base + (size_t)t*HW];
        float gv  = g_gt[base + (size_t)t*HW];
        float2 e  = (t < 8) ? tw16[t] : make_float2(-tw16[t-8].x, -tw16[t-8].y); // e^{-2pi i t/16}
        float2 ec = make_float2(e.x, -e.y);
        float2 Af = cadd(cadd(cmul(sA[0], ec), sA[1]), cmul(sA[2], e));
        float2 Bf = cadd(cadd(cmul(sB[0], ec), sB[1]), cmul(sB[2], e));
        float2 bx = cmul(Bf, v[t]);
        float2 an = make_float2(fgv*Af.x, fgv*Af.y);
        hacc = cadd(cmul(an, hacc), make_float2(gv*bx.x, gv*bx.y));
        v[t] = hacc;
    }
    fft16r<true>(v, tw16);
    #pragma unroll
    for (int t=0;t<16;t++){
        v[t].x *= 0.0625f; v[t].y *= 0.0625f;   // 1/16 of the ifftn scale
        g_xf[base + (size_t)t*HW] = v[t];
    }
}

// ---------------- P4: inverse 2D FFT (h,w) per (b,c,t), keep real ----------
__global__ __launch_bounds__(256) void k_ifft()
{
    __shared__ float2 S[64*65];
    __shared__ float2 tw[32];
    int tid = threadIdx.x;
    if (tid < 32){
        float s, c;
        sincosf(-6.283185307179586f * (float)tid / 64.f, &s, &c);
        tw[tid] = make_float2(c, s);
    }
    const float2* src = g_xf + (size_t)blockIdx.x * HW;
    float* dst = g_xr + (size_t)blockIdx.x * HW;   // reuse g_xr for real output
    for (int idx = tid; idx < 4096; idx += 256)
        S[(idx >> 6)*65 + (idx & 63)] = src[idx];
    __syncthreads();
    fft64_batch<true>(S, tw, tid, 65, 1);
    fft64_batch<true>(S, tw, tid, 1, 65);
    const float scale = 1.f / 4096.f;              // 1/(64*64) of the ifftn scale
    for (int idx = tid; idx < 4096; idx += 256)
        dst[idx] = S[(idx >> 6)*65 + (idx & 63)].x * scale;
}

// ---------------- P5: transpose (b,c,t,h,w) -> (b,t,h,w,c) ----------------
__global__ __launch_bounds__(256) void k_out(float* __restrict__ out)
{
    __shared__ float S[64][65];  // [c][w]
    int tid = threadIdx.x;
    int blk = blockIdx.x;                  // ((b*16+t)*64 + h)
    int h = blk & 63, bt = blk >> 6, t = bt & 15, b = bt >> 4;
    size_t ibase = (size_t)b*((size_t)NC*THW) + (size_t)t*HW + (size_t)h*NW;
    for (int idx = tid; idx < 4096; idx += 256){
        int c = idx >> 6, w = idx & 63;
        S[c][w] = g_xr[ibase + (size_t)c*THW + w];
    }
    __syncthreads();
    float* orow = out + (size_t)blk * (NW*NC);
    for (int idx = tid; idx < 4096; idx += 256){
        int w = idx >> 6, c = idx & 63;
        orow[idx] = S[c][w];
    }
}

extern "C" void kernel_launch(void* const* d_in, const int* in_sizes, int n_in,
                              void* d_out, int out_size)
{
    const float* x   = (const float*)d_in[0];
    const float* Ak  = (const float*)d_in[1];
    const float* Bk  = (const float*)d_in[2];
    const float* fb  = (const float*)d_in[3];
    const float* fs  = (const float*)d_in[4];
    const float* ib  = (const float*)d_in[5];
    const float* isc = (const float*)d_in[6];
    const float* dW  = (const float*)d_in[7];
    const float* db  = (const float*)d_in[8];
    float* out = (float*)d_out;

    k_gates<<<2048, 256>>>(x, dW, db, fb, fs, ib, isc);   // (b,t,h) rows
    k_fft_fwd<<<2048, 256>>>();                           // (b,c,t) slices
    k_tscan<<<dim3(16, 64, 2), 256>>>(Ak, Bk);            // (hw/256, c, b)
    k_ifft<<<2048, 256>>>();                              // (b,c,t) slices
    k_out<<<2048, 256>>>(out);                            // (b,t,h) rows
}

// round 5
// speedup vs baseline: 1.5505x; 1.5505x over previous
#include <cuda_runtime.h>
#include <math.h>

#define NB 2
#define NT 16
#define NH 64
#define NW 64
#define NC 64
#define HW 4096      // NH*NW
#define THW 65536    // NT*HW
#define TOT 8388608  // NB*NC*THW

// Scratch (allocation-free rule: __device__ globals).
static __device__ float  g_xr[TOT];    // real x transposed (b,c,t,h,w); reused for IFFT output
static __device__ float2 g_gate[TOT];  // (forget_gate, input_gate*delta), (b,c,t,h,w)
static __device__ float2 g_xf[TOT];    // complex work array (b,c,t,h,w)

__device__ __forceinline__ float2 cmul(float2 a, float2 b){
    return make_float2(a.x*b.x - a.y*b.y, a.x*b.y + a.y*b.x);
}
__device__ __forceinline__ float2 cadd(float2 a, float2 b){ return make_float2(a.x+b.x, a.y+b.y); }
__device__ __forceinline__ float2 csub(float2 a, float2 b){ return make_float2(a.x-b.x, a.y-b.y); }

// ---------------- P1: gates + delta GEMM + transpose ----------------
__global__ __launch_bounds__(256) void k_gates(
    const float* __restrict__ x, const float* __restrict__ dW,
    const float* __restrict__ db, const float* __restrict__ fb,
    const float* __restrict__ fs, const float* __restrict__ ib,
    const float* __restrict__ isc)
{
    __shared__ float Xs[64][65];   // [w][c]
    __shared__ float Ds[64][65];   // [w][d]  (softplus(delta))
    int tid = threadIdx.x;
    int blk = blockIdx.x;                  // ((b*16+t)*64 + h)
    int h = blk & 63, bt = blk >> 6, t = bt & 15, b = bt >> 4;
    const float* xrow = x + (size_t)blk * (NW*NC);

    for (int idx = tid; idx < 4096; idx += 256)
        Xs[idx >> 6][idx & 63] = xrow[idx];
    __syncthreads();

    int d0 = (tid & 15) << 2;
    int w0 = (tid >> 4) << 2;
    float acc[4][4];
    #pragma unroll
    for (int i=0;i<4;i++)
        #pragma unroll
        for (int j=0;j<4;j++) acc[i][j] = 0.f;
    #pragma unroll 4
    for (int c=0;c<64;c++){
        float4 wv = __ldg((const float4*)(dW + c*64 + d0));
        float xs0 = Xs[w0+0][c], xs1 = Xs[w0+1][c];
        float xs2 = Xs[w0+2][c], xs3 = Xs[w0+3][c];
        acc[0][0]=fmaf(xs0,wv.x,acc[0][0]); acc[0][1]=fmaf(xs0,wv.y,acc[0][1]);
        acc[0][2]=fmaf(xs0,wv.z,acc[0][2]); acc[0][3]=fmaf(xs0,wv.w,acc[0][3]);
        acc[1][0]=fmaf(xs1,wv.x,acc[1][0]); acc[1][1]=fmaf(xs1,wv.y,acc[1][1]);
        acc[1][2]=fmaf(xs1,wv.z,acc[1][2]); acc[1][3]=fmaf(xs1,wv.w,acc[1][3]);
        acc[2][0]=fmaf(xs2,wv.x,acc[2][0]); acc[2][1]=fmaf(xs2,wv.y,acc[2][1]);
        acc[2][2]=fmaf(xs2,wv.z,acc[2][2]); acc[2][3]=fmaf(xs2,wv.w,acc[2][3]);
        acc[3][0]=fmaf(xs3,wv.x,acc[3][0]); acc[3][1]=fmaf(xs3,wv.y,acc[3][1]);
        acc[3][2]=fmaf(xs3,wv.z,acc[3][2]); acc[3][3]=fmaf(xs3,wv.w,acc[3][3]);
    }
    #pragma unroll
    for (int j=0;j<4;j++){
        float bias = __ldg(db + d0 + j);
        #pragma unroll
        for (int i=0;i<4;i++){
            float z = acc[i][j] + bias;
            Ds[w0+i][d0+j] = (z > 20.f) ? z : log1pf(__expf(z));  // softplus
        }
    }
    __syncthreads();

    size_t obase = (size_t)b*((size_t)NC*THW) + (size_t)t*HW + (size_t)h*NW;
    for (int idx = tid; idx < 4096; idx += 256){
        int c = idx >> 6, w = idx & 63;
        float xv = Xs[w][c];
        size_t o = obase + (size_t)c*THW + w;
        g_xr[o] = xv;
        float fgv = 1.f/(1.f + __expf(-(__ldg(fb+c)  + __ldg(fs+c) *xv)));
        float igv = 1.f/(1.f + __expf(-(__ldg(ib+c)  + __ldg(isc+c)*xv)));
        g_gate[o] = make_float2(fgv, igv * Ds[w][c]);
    }
}

// ---------------- radix-8 building blocks ----------------
__device__ __constant__ int BREV8[8] = {0,4,2,6,1,5,3,7};

template<bool INV>
__device__ __forceinline__ void dft8(float xr[8], float xi[8]){
    const float IS = INV ? 1.f : -1.f;
    const float R2 = 0.70710678118654752f;
    float ur,ui,vr,vi,dr,di;
    // stage A (span 4)
    ur=xr[0]; ui=xi[0]; vr=xr[4]; vi=xi[4];
    xr[0]=ur+vr; xi[0]=ui+vi; xr[4]=ur-vr; xi[4]=ui-vi;
    ur=xr[1]; ui=xi[1]; vr=xr[5]; vi=xi[5];
    xr[1]=ur+vr; xi[1]=ui+vi; dr=ur-vr; di=ui-vi;
    xr[5]=R2*(dr - IS*di); xi[5]=R2*(IS*dr + di);
    ur=xr[2]; ui=xi[2]; vr=xr[6]; vi=xi[6];
    xr[2]=ur+vr; xi[2]=ui+vi; dr=ur-vr; di=ui-vi;
    xr[6]=-IS*di; xi[6]=IS*dr;
    ur=xr[3]; ui=xi[3]; vr=xr[7]; vi=xi[7];
    xr[3]=ur+vr; xi[3]=ui+vi; dr=ur-vr; di=ui-vi;
    xr[7]=-R2*(dr + IS*di); xi[7]=R2*(IS*dr - di);
    // stage B (span 2)
    ur=xr[0]; ui=xi[0]; vr=xr[2]; vi=xi[2];
    xr[0]=ur+vr; xi[0]=ui+vi; xr[2]=ur-vr; xi[2]=ui-vi;
    ur=xr[1]; ui=xi[1]; vr=xr[3]; vi=xi[3];
    xr[1]=ur+vr; xi[1]=ui+vi; dr=ur-vr; di=ui-vi;
    xr[3]=-IS*di; xi[3]=IS*dr;
    ur=xr[4]; ui=xi[4]; vr=xr[6]; vi=xi[6];
    xr[4]=ur+vr; xi[4]=ui+vi; xr[6]=ur-vr; xi[6]=ui-vi;
    ur=xr[5]; ui=xi[5]; vr=xr[7]; vi=xi[7];
    xr[5]=ur+vr; xi[5]=ui+vi; dr=ur-vr; di=ui-vi;
    xr[7]=-IS*di; xi[7]=IS*dr;
    // stage C (span 1)
    ur=xr[0]; ui=xi[0]; vr=xr[1]; vi=xi[1];
    xr[0]=ur+vr; xi[0]=ui+vi; xr[1]=ur-vr; xi[1]=ui-vi;
    ur=xr[2]; ui=xi[2]; vr=xr[3]; vi=xi[3];
    xr[2]=ur+vr; xi[2]=ui+vi; xr[3]=ur-vr; xi[3]=ui-vi;
    ur=xr[4]; ui=xi[4]; vr=xr[5]; vi=xi[5];
    xr[4]=ur+vr; xi[4]=ui+vi; xr[5]=ur-vr; xi[5]=ui-vi;
    ur=xr[6]; ui=xi[6]; vr=xr[7]; vi=xi[7];
    xr[6]=ur+vr; xi[6]=ui+vi; xr[7]=ur-vr; xi[7]=ui-vi;
}

// twiddles W64^{n2*k}, k=0..7 (conjugated for INV)
template<bool INV>
__device__ __forceinline__ void twgen(int n2, float wr[8], float wi[8]){
    float s, c;
    sincosf((INV ? 6.283185307179586f : -6.283185307179586f) * (float)n2 * (1.f/64.f), &s, &c);
    wr[0]=1.f; wi[0]=0.f; wr[1]=c; wi[1]=s;
    #pragma unroll
    for (int k=2;k<8;k++){
        wr[k]=wr[k-1]*c - wi[k-1]*s;
        wi[k]=wr[k-1]*s + wi[k-1]*c;
    }
}

// ---------------- P2/P4: 2D 64x64 FFT per (b,c,t) slice --------------------
// Two-stage radix-8 four-step along w, then along h.
// smem: SoA float, row stride 72 -> bank = (8r + c) & 31; all patterns verified
// conflict-free. Only one __syncthreads per block (w->h handoff).
template<bool INV>
__global__ __launch_bounds__(256) void k_fft2d()
{
    __shared__ float SR[64*72], SI[64*72];
    const int tid = threadIdx.x;
    const size_t sbase = (size_t)blockIdx.x * HW;

    // ---- w direction, stage 1: gmem -> regs -> DFT8 -> twiddle -> smem(swizzled)
    {
        const int r4 = tid >> 3, n2 = tid & 7;
        float wr[8], wi[8]; twgen<INV>(n2, wr, wi);
        #pragma unroll
        for (int rr=0; rr<2; rr++){
            const int r = r4 + 32*rr;
            float xr[8], xi[8];
            #pragma unroll
            for (int j=0;j<8;j++){
                if (INV){
                    float2 v = g_xf[sbase + r*64 + 8*j + n2];
                    xr[j]=v.x; xi[j]=v.y;
                } else {
                    xr[j] = g_xr[sbase + r*64 + 8*j + n2]; xi[j] = 0.f;
                }
            }
            dft8<INV>(xr, xi);
            #pragma unroll
            for (int p=0;p<8;p++){
                const int k1 = BREV8[p];
                float yr = xr[p]*wr[k1] - xi[p]*wi[k1];
                float yi = xr[p]*wi[k1] + xi[p]*wr[k1];
                const int col = 8*n2 + ((k1+n2)&7);
                SR[r*72+col]=yr; SI[r*72+col]=yi;
            }
        }
    }
    __syncwarp();
    // ---- w direction, stage 2: smem(swizzled) -> DFT8 -> smem(natural cols)
    {
        const int r4 = tid >> 3, k1 = tid & 7;
        #pragma unroll
        for (int rr=0; rr<2; rr++){
            const int r = r4 + 32*rr;
            float zr[8], zi[8];
            #pragma unroll
            for (int n2=0;n2<8;n2++){
                const int col = 8*n2 + ((k1+n2)&7);
                zr[n2]=SR[r*72+col]; zi[n2]=SI[r*72+col];
            }
            __syncwarp();
            dft8<INV>(zr, zi);
            #pragma unroll
            for (int p=0;p<8;p++){
                const int k2 = BREV8[p];
                const int col = k1 + 8*k2;
                SR[r*72+col]=zr[p]; SI[r*72+col]=zi[p];
            }
        }
    }
    __syncthreads();
    // ---- h direction, stage 1: preload both halves, DFT8 + twiddle -> smem(swizzled rows)
    {
        const int c = ((tid>>5)<<3) | (tid&7);
        const int q = (tid>>3)&3;
        float ar[8], ai[8], br8[8], bi8[8];
        #pragma unroll
        for (int j=0;j<8;j++){
            const int row0 = 8*j + q;
            ar[j]=SR[row0*72+c]; ai[j]=SI[row0*72+c];
            const int row1 = 8*j + q + 4;
            br8[j]=SR[row1*72+c]; bi8[j]=SI[row1*72+c];
        }
        __syncwarp();
        {   // half 0: n2 = q
            float wr[8], wi[8]; twgen<INV>(q, wr, wi);
            dft8<INV>(ar, ai);
            #pragma unroll
            for (int p=0;p<8;p++){
                const int k1 = BREV8[p];
                float yr = ar[p]*wr[k1] - ai[p]*wi[k1];
                float yi = ar[p]*wi[k1] + ai[p]*wr[k1];
                const int row = 8*q + ((k1+q)&7);
                SR[row*72+c]=yr; SI[row*72+c]=yi;
            }
        }
        {   // half 1: n2 = q+4
            const int n2 = q + 4;
            float wr[8], wi[8]; twgen<INV>(n2, wr, wi);
            dft8<INV>(br8, bi8);
            #pragma unroll
            for (int p=0;p<8;p++){
                const int k1 = BREV8[p];
                float yr = br8[p]*wr[k1] - bi8[p]*wi[k1];
                float yi = br8[p]*wi[k1] + bi8[p]*wr[k1];
                const int row = 8*n2 + ((k1+n2)&7);
                SR[row*72+c]=yr; SI[row*72+c]=yi;
            }
        }
    }
    __syncwarp();
    // ---- h direction, stage 2: smem(swizzled rows) -> DFT8 -> gmem (natural)
    {
        const int c = ((tid>>5)<<3) | (tid&7);
        const int q = (tid>>3)&3;
        #pragma unroll
        for (int half=0; half<2; half++){
            const int k1 = q + 4*half;
            float zr[8], zi[8];
            #pragma unroll
            for (int n2=0;n2<8;n2++){
                const int row = 8*n2 + ((k1+n2)&7);
                zr[n2]=SR[row*72+c]; zi[n2]=SI[row*72+c];
            }
            dft8<INV>(zr, zi);
            #pragma unroll
            for (int p=0;p<8;p++){
                const int k2 = BREV8[p];
                const int orow = k1 + 8*k2;
                if (INV){
                    g_xr[sbase + orow*64 + c] = zr[p] * (1.f/4096.f);
                } else {
                    g_xf[sbase + orow*64 + c] = make_float2(zr[p], zi[p]);
                }
            }
        }
    }
}

// ---------------- 16-pt register FFT ----------------
template<bool INV>
__device__ __forceinline__ void fft16r(float2* v, const float2* tw)
{
    const int rev[16] = {0,8,4,12,2,10,6,14,1,9,5,13,3,11,7,15};
    #pragma unroll
    for (int i=0;i<16;i++){
        int j = rev[i];
        if (i < j){ float2 tmp = v[i]; v[i] = v[j]; v[j] = tmp; }
    }
    #pragma unroll
    for (int st=1; st<=4; ++st){
        const int m = 1<<st, mh = m>>1;
        #pragma unroll
        for (int g=0; g<16; g+=m){
            #pragma unroll
            for (int j=0;j<mh;++j){
                float2 w = tw[j*(16/m)];
                if (INV) w.y = -w.y;
                float2 u = v[g+j];
                float2 t2 = cmul(v[g+j+mh], w);
                v[g+j]    = cadd(u, t2);
                v[g+j+mh] = csub(u, t2);
            }
        }
    }
}

// ---------------- P3: T-FFT + Mamba scan + T-IFFT (fused, in registers) ----
__global__ __launch_bounds__(256) void k_tscan(const float* __restrict__ Ak,
                                               const float* __restrict__ Bk)
{
    __shared__ float sKA[27], sKB[27];
    int tid = threadIdx.x;
    int c = blockIdx.y, b = blockIdx.z;
    if (tid < 27){ sKA[tid] = Ak[c*27+tid]; sKB[tid] = Bk[c*27+tid]; }
    __syncthreads();
    int hw = blockIdx.x*256 + tid;
    int h = hw >> 6, w = hw & 63;

    // e^{-2pi i k/16}, k=0..7 (compile-time constants, no MUFU)
    const float TWR[8] = {1.f, 0.9238795325112867f, 0.7071067811865476f, 0.3826834323650898f,
                          0.f, -0.3826834323650898f, -0.7071067811865476f, -0.9238795325112867f};
    const float TWI[8] = {0.f, -0.3826834323650898f, -0.7071067811865476f, -0.9238795325112867f,
                          -1.f, -0.9238795325112867f, -0.7071067811865476f, -0.3826834323650898f};
    float2 tw16[8];
    #pragma unroll
    for (int k=0;k<8;k++) tw16[k] = make_float2(TWR[k], TWI[k]);

    float2 eh, ew;
    { float s,cc; sincosf(-0.09817477042468103f*(float)h, &s, &cc); eh = make_float2(cc,s); }
    { float s,cc; sincosf(-0.09817477042468103f*(float)w, &s, &cc); ew = make_float2(cc,s); }
    float2 eh3[3] = { make_float2(eh.x,-eh.y), make_float2(1.f,0.f), eh };
    float2 ew3[3] = { make_float2(ew.x,-ew.y), make_float2(1.f,0.f), ew };

    float2 sA[3], sB[3];
    #pragma unroll
    for (int dt=0;dt<3;dt++){
        float2 a = make_float2(0.f,0.f), bb = make_float2(0.f,0.f);
        #pragma unroll
        for (int dh=0;dh<3;dh++){
            #pragma unroll
            for (int dw=0;dw<3;dw++){
                float2 e = cmul(eh3[dh], ew3[dw]);
                float ka = sKA[dt*9+dh*3+dw], kb = sKB[dt*9+dh*3+dw];
                a.x  = fmaf(ka, e.x, a.x);  a.y  = fmaf(ka, e.y, a.y);
                bb.x = fmaf(kb, e.x, bb.x); bb.y = fmaf(kb, e.y, bb.y);
            }
        }
        sA[dt]=a; sB[dt]=bb;
    }

    size_t base = ((size_t)(b*NC + c))*THW + (size_t)hw;
    float2 v[16];
    #pragma unroll
    for (int t=0;t<16;t++) v[t] = g_xf[base + (size_t)t*HW];
    fft16r<false>(v, tw16);

    float2 hacc = make_float2(0.f, 0.f);
    #pragma unroll
    for (int t=0;t<16;t++){
        float2 gg = g_gate[base + (size_t)t*HW];
        float fgv = gg.x, gv = gg.y;
        float2 e  = (t < 8) ? tw16[t] : make_float2(-tw16[t-8].x, -tw16[t-8].y);
        float2 ec = make_float2(e.x, -e.y);
        float2 Af = cadd(cadd(cmul(sA[0], ec), sA[1]), cmul(sA[2], e));
        float2 Bf = cadd(cadd(cmul(sB[0], ec), sB[1]), cmul(sB[2], e));
        float2 bx = cmul(Bf, v[t]);
        float2 an = make_float2(fgv*Af.x, fgv*Af.y);
        hacc = cadd(cmul(an, hacc), make_float2(gv*bx.x, gv*bx.y));
        v[t] = hacc;
    }
    fft16r<true>(v, tw16);
    #pragma unroll
    for (int t=0;t<16;t++){
        v[t].x *= 0.0625f; v[t].y *= 0.0625f;
        g_xf[base + (size_t)t*HW] = v[t];
    }
}

// ---------------- P5: transpose (b,c,t,h,w) -> (b,t,h,w,c) ----------------
__global__ __launch_bounds__(256) void k_out(float* __restrict__ out)
{
    __shared__ float S[64][65];  // [c][w]
    int tid = threadIdx.x;
    int blk = blockIdx.x;                  // ((b*16+t)*64 + h)
    int h = blk & 63, bt = blk >> 6, t = bt & 15, b = bt >> 4;
    size_t ibase = (size_t)b*((size_t)NC*THW) + (size_t)t*HW + (size_t)h*NW;
    for (int idx = tid; idx < 4096; idx += 256){
        int c = idx >> 6, w = idx & 63;
        S[c][w] = g_xr[ibase + (size_t)c*THW + w];
    }
    __syncthreads();
    float* orow = out + (size_t)blk * (NW*NC);
    for (int idx = tid; idx < 4096; idx += 256){
        int w = idx >> 6, c = idx & 63;
        orow[idx] = S[c][w];
    }
}

extern "C" void kernel_launch(void* const* d_in, const int* in_sizes, int n_in,
                              void* d_out, int out_size)
{
    const float* x   = (const float*)d_in[0];
    const float* Ak  = (const float*)d_in[1];
    const float* Bk  = (const float*)d_in[2];
    const float* fb  = (const float*)d_in[3];
    const float* fs  = (const float*)d_in[4];
    const float* ib  = (const float*)d_in[5];
    const float* isc = (const float*)d_in[6];
    const float* dW  = (const float*)d_in[7];
    const float* db  = (const float*)d_in[8];
    float* out = (float*)d_out;

    k_gates<<<2048, 256>>>(x, dW, db, fb, fs, ib, isc);   // (b,t,h) rows
    k_fft2d<false><<<2048, 256>>>();                      // forward 2D FFT per (b,c,t)
    k_tscan<<<dim3(16, 64, 2), 256>>>(Ak, Bk);            // (hw/256, c, b)
    k_fft2d<true><<<2048, 256>>>();                       // inverse 2D FFT per (b,c,t)
    k_out<<<2048, 256>>>(out);                            // transpose to output
}